// round 2
// baseline (speedup 1.0000x reference)
#include <cuda_runtime.h>
#include <cuda_bf16.h>

#define D_IN   128
#define D_OUT  64
#define MAXN   50000

// Scratch (no cudaMalloc allowed): per relation, projected-src features and accumulator.
// g_T[r][i*64+c]   = (x_r[i] @ Wrel_r^T)[c]
// g_ACC[r][i*64+c] = (x_r[i] @ Wroot_r^T)[c] + brel_r[c]   (then scatter-added into)
__device__ float g_T[2][MAXN * D_OUT];
__device__ float g_ACC[2][MAXN * D_OUT];

// ---------------------------------------------------------------------------
// Kernel A: fused dual-projection GEMM.
// Computes a [128-row x 128-col] tile of  X[N,128] @ Wc^T  where
// Wc rows 0..63 = Wrel (-> g_T), rows 64..127 = Wroot (+brel -> g_ACC).
// 256 threads, 8x8 register tile per thread, K tiled by 32.
// ---------------------------------------------------------------------------
__global__ __launch_bounds__(256) void transform_kernel(
    const float* __restrict__ X,
    const float* __restrict__ Wrel,
    const float* __restrict__ brel,
    const float* __restrict__ Wroot,
    int rel, int N)
{
    __shared__ float Ws[32][128];   // Ws[k][c] = Wc[c][kb+k]
    __shared__ float Xs[128][33];   // Xs[r][k], padded
    __shared__ float bs[64];

    const int tid = threadIdx.x;
    const int tx  = tid & 15;   // col group: cols tx*8 .. tx*8+7
    const int ty  = tid >> 4;   // row group: rows ty*8 .. ty*8+7
    const int row0 = blockIdx.x * 128;

    if (tid < 64) bs[tid] = brel[tid];

    float acc[8][8];
#pragma unroll
    for (int i = 0; i < 8; i++)
#pragma unroll
        for (int j = 0; j < 8; j++) acc[i][j] = 0.0f;

    for (int kc = 0; kc < 4; kc++) {
        const int kb = kc * 32;

        // Load Ws[k][c] (transposed). 4096 floats as 1024 float4-over-k.
#pragma unroll
        for (int i = 0; i < 4; i++) {
            int idx = tid + i * 256;
            int c   = idx & 127;
            int kq  = idx >> 7;              // 0..7
            const float* wsrc = (c < 64) ? (Wrel + c * D_IN)
                                         : (Wroot + (c - 64) * D_IN);
            float4 w = *(const float4*)(wsrc + kb + kq * 4);
            Ws[kq * 4 + 0][c] = w.x;
            Ws[kq * 4 + 1][c] = w.y;
            Ws[kq * 4 + 2][c] = w.z;
            Ws[kq * 4 + 3][c] = w.w;
        }

        // Load Xs[r][k]. Coalesced global float4 reads along k.
#pragma unroll
        for (int i = 0; i < 4; i++) {
            int idx = tid + i * 256;
            int r   = idx >> 3;              // 0..127
            int kq  = idx & 7;               // 0..7
            int grow = row0 + r;
            float4 v = make_float4(0.f, 0.f, 0.f, 0.f);
            if (grow < N) v = *(const float4*)(X + (long)grow * D_IN + kb + kq * 4);
            Xs[r][kq * 4 + 0] = v.x;
            Xs[r][kq * 4 + 1] = v.y;
            Xs[r][kq * 4 + 2] = v.z;
            Xs[r][kq * 4 + 3] = v.w;
        }

        __syncthreads();

#pragma unroll
        for (int k = 0; k < 32; k++) {
            float a[8];
#pragma unroll
            for (int i = 0; i < 8; i++) a[i] = Xs[ty * 8 + i][k];
            float4 b0 = *(const float4*)&Ws[k][tx * 8];
            float4 b1 = *(const float4*)&Ws[k][tx * 8 + 4];
            float b[8] = {b0.x, b0.y, b0.z, b0.w, b1.x, b1.y, b1.z, b1.w};
#pragma unroll
            for (int i = 0; i < 8; i++)
#pragma unroll
                for (int j = 0; j < 8; j++) acc[i][j] = fmaf(a[i], b[j], acc[i][j]);
        }
        __syncthreads();
    }

    // Epilogue: cols<64 -> g_T ; cols>=64 -> g_ACC (+brel). tx<8 <=> rel-part.
    float* Tout = g_T[rel];
    float* Aout = g_ACC[rel];
#pragma unroll
    for (int i = 0; i < 8; i++) {
        int row = row0 + ty * 8 + i;
        if (row >= N) break;
        if (tx < 8) {
            int c = tx * 8;
            float4 v0 = make_float4(acc[i][0], acc[i][1], acc[i][2], acc[i][3]);
            float4 v1 = make_float4(acc[i][4], acc[i][5], acc[i][6], acc[i][7]);
            *(float4*)(Tout + (long)row * D_OUT + c)     = v0;
            *(float4*)(Tout + (long)row * D_OUT + c + 4) = v1;
        } else {
            int c = (tx - 8) * 8;
            float4 v0 = make_float4(acc[i][0] + bs[c + 0], acc[i][1] + bs[c + 1],
                                    acc[i][2] + bs[c + 2], acc[i][3] + bs[c + 3]);
            float4 v1 = make_float4(acc[i][4] + bs[c + 4], acc[i][5] + bs[c + 5],
                                    acc[i][6] + bs[c + 6], acc[i][7] + bs[c + 7]);
            *(float4*)(Aout + (long)row * D_OUT + c)     = v0;
            *(float4*)(Aout + (long)row * D_OUT + c + 4) = v1;
        }
    }
}

// ---------------------------------------------------------------------------
// Kernel B: edge scatter-add in projected (64-dim) space.
// 16 threads per edge, each handles one float4 chunk; vector red to L2.
// NOTE: edges are int32 (JAX default x64-disabled downcasts int64 -> int32).
// ---------------------------------------------------------------------------
__global__ __launch_bounds__(256) void scatter_kernel(
    const int* __restrict__ edges,   // [2][E] int32
    int rel, int E)
{
    const float* __restrict__ T = g_T[rel];
    float* __restrict__ A = g_ACC[rel];

    int idx  = blockIdx.x * blockDim.x + threadIdx.x;
    int e    = idx >> 4;
    int lane = idx & 15;
    if (e >= E) return;

    int src = edges[e];
    int dst = edges[E + e];

    float4 v = *(const float4*)(T + (long)src * D_OUT + lane * 4);
    float* p = A + (long)dst * D_OUT + lane * 4;
    asm volatile("red.global.add.v4.f32 [%0], {%1,%2,%3,%4};"
                 :: "l"(p), "f"(v.x), "f"(v.y), "f"(v.z), "f"(v.w)
                 : "memory");
}

// ---------------------------------------------------------------------------
// Kernel C: fused relu + concat-dot with Wfc + bias. 16 threads per node.
// ---------------------------------------------------------------------------
__global__ __launch_bounds__(256) void output_kernel(
    const float* __restrict__ Wfc,   // [1][128]
    const float* __restrict__ bfc,   // [1]
    float* __restrict__ out, int N)
{
    __shared__ float wf[128];
    int tid = threadIdx.x;
    if (tid < 128) wf[tid] = Wfc[tid];
    __syncthreads();

    int idx  = blockIdx.x * blockDim.x + tid;
    int node = idx >> 4;
    int lane = idx & 15;
    if (node >= N) return;

    float4 a = *(const float4*)(g_ACC[0] + (long)node * D_OUT + lane * 4);
    float4 b = *(const float4*)(g_ACC[1] + (long)node * D_OUT + lane * 4);

    int c = lane * 4;
    float s = 0.0f;
    s += fmaxf(a.x, 0.f) * wf[c + 0];
    s += fmaxf(a.y, 0.f) * wf[c + 1];
    s += fmaxf(a.z, 0.f) * wf[c + 2];
    s += fmaxf(a.w, 0.f) * wf[c + 3];
    s += fmaxf(b.x, 0.f) * wf[64 + c + 0];
    s += fmaxf(b.y, 0.f) * wf[64 + c + 1];
    s += fmaxf(b.z, 0.f) * wf[64 + c + 2];
    s += fmaxf(b.w, 0.f) * wf[64 + c + 3];

#pragma unroll
    for (int off = 8; off > 0; off >>= 1)
        s += __shfl_down_sync(0xFFFFFFFFu, s, off, 16);

    if (lane == 0) out[node] = s + bfc[0];
}

// ---------------------------------------------------------------------------
extern "C" void kernel_launch(void* const* d_in, const int* in_sizes, int n_in,
                              void* d_out, int out_size)
{
    const float* x0     = (const float*)d_in[0];
    const float* x1     = (const float*)d_in[1];
    const int*   e0     = (const int*)d_in[2];
    const int*   e1     = (const int*)d_in[3];
    const float* Wrel0  = (const float*)d_in[4];
    const float* brel0  = (const float*)d_in[5];
    const float* Wroot0 = (const float*)d_in[6];
    const float* Wrel1  = (const float*)d_in[7];
    const float* brel1  = (const float*)d_in[8];
    const float* Wroot1 = (const float*)d_in[9];
    const float* Wfc    = (const float*)d_in[10];
    const float* bfc    = (const float*)d_in[11];
    float* out = (float*)d_out;

    const int N = in_sizes[0] / D_IN;     // 50000
    const int E = in_sizes[2] / 2;        // 600000

    const int tblocks = (N + 127) / 128;
    const int sblocks = (E * 16 + 255) / 256;
    const int oblocks = (N * 16 + 255) / 256;

    // rel0 fully before rel1 so g_T[0] stays L2-hot for its scatter.
    transform_kernel<<<tblocks, 256>>>(x0, Wrel0, brel0, Wroot0, 0, N);
    scatter_kernel<<<sblocks, 256>>>(e0, 0, E);
    transform_kernel<<<tblocks, 256>>>(x1, Wrel1, brel1, Wroot1, 1, N);
    scatter_kernel<<<sblocks, 256>>>(e1, 1, E);
    output_kernel<<<oblocks, 256>>>(Wfc, bfc, out, N);
}

// round 3
// speedup vs baseline: 1.0720x; 1.0720x over previous
#include <cuda_runtime.h>
#include <cuda_bf16.h>

#define D_IN   128
#define D_OUT  64
#define MAXN   50000

typedef unsigned long long u64;

__device__ float g_T[2][MAXN * D_OUT];
__device__ float g_ACC[2][MAXN * D_OUT];

__device__ __forceinline__ void fma2(u64& d, u64 a, u64 b) {
    asm("fma.rn.f32x2 %0, %1, %2, %3;" : "=l"(d) : "l"(a), "l"(b), "l"(d));
}
__device__ __forceinline__ u64 pack_dup(float x) {
    u64 r; asm("mov.b64 %0, {%1, %1};" : "=l"(r) : "f"(x)); return r;
}
__device__ __forceinline__ u64 pack2(float lo, float hi) {
    u64 r; asm("mov.b64 %0, {%1, %2};" : "=l"(r) : "f"(lo), "f"(hi)); return r;
}
__device__ __forceinline__ void unpack2(u64 v, float& lo, float& hi) {
    asm("mov.b64 {%0, %1}, %2;" : "=f"(lo), "=f"(hi) : "l"(v));
}

// ---------------------------------------------------------------------------
// Kernel A: fused dual-projection GEMM for BOTH relations (grid.y = rel).
// [128 x 128] tile of X[N,128] @ Wc^T; Wc rows 0..63 = Wrel (-> g_T),
// rows 64..127 = Wroot (+brel -> g_ACC). Packed f32x2 FMA mainloop.
// ---------------------------------------------------------------------------
__global__ __launch_bounds__(256, 2) void transform_kernel(
    const float* __restrict__ X0, const float* __restrict__ X1,
    const float* __restrict__ Wrel0, const float* __restrict__ brel0,
    const float* __restrict__ Wroot0,
    const float* __restrict__ Wrel1, const float* __restrict__ brel1,
    const float* __restrict__ Wroot1,
    int N)
{
    __shared__ float Ws[32][128];   // Ws[k][c]
    __shared__ float Xs[128][33];   // Xs[r][k]
    __shared__ float bs[64];

    const int rel = blockIdx.y;
    const float* __restrict__ X     = rel ? X1 : X0;
    const float* __restrict__ Wrel  = rel ? Wrel1 : Wrel0;
    const float* __restrict__ brel  = rel ? brel1 : brel0;
    const float* __restrict__ Wroot = rel ? Wroot1 : Wroot0;

    const int tid = threadIdx.x;
    const int tx  = tid & 15;   // cols tx*8 .. tx*8+7
    const int ty  = tid >> 4;   // rows ty*8 .. ty*8+7
    const int row0 = blockIdx.x * 128;

    if (tid < 64) bs[tid] = brel[tid];

    u64 acc[8][4];  // packed pairs over the 8-column dim
#pragma unroll
    for (int i = 0; i < 8; i++)
#pragma unroll
        for (int j = 0; j < 4; j++) acc[i][j] = 0ull;

    for (int kc = 0; kc < 4; kc++) {
        const int kb = kc * 32;

        // Ws[k][c] (transposed weight). 4096 floats via float4-over-k.
#pragma unroll
        for (int i = 0; i < 4; i++) {
            int idx = tid + i * 256;
            int c   = idx & 127;
            int kq  = idx >> 7;
            const float* wsrc = (c < 64) ? (Wrel + c * D_IN)
                                         : (Wroot + (c - 64) * D_IN);
            float4 w = *(const float4*)(wsrc + kb + kq * 4);
            Ws[kq * 4 + 0][c] = w.x;
            Ws[kq * 4 + 1][c] = w.y;
            Ws[kq * 4 + 2][c] = w.z;
            Ws[kq * 4 + 3][c] = w.w;
        }

        // Xs[r][k], coalesced float4 reads.
#pragma unroll
        for (int i = 0; i < 4; i++) {
            int idx = tid + i * 256;
            int r   = idx >> 3;
            int kq  = idx & 7;
            int grow = row0 + r;
            float4 v = make_float4(0.f, 0.f, 0.f, 0.f);
            if (grow < N) v = *(const float4*)(X + (long)grow * D_IN + kb + kq * 4);
            Xs[r][kq * 4 + 0] = v.x;
            Xs[r][kq * 4 + 1] = v.y;
            Xs[r][kq * 4 + 2] = v.z;
            Xs[r][kq * 4 + 3] = v.w;
        }

        __syncthreads();

#pragma unroll
        for (int k = 0; k < 32; k++) {
            u64 a2[8];
#pragma unroll
            for (int i = 0; i < 8; i++) a2[i] = pack_dup(Xs[ty * 8 + i][k]);

            float4 b0 = *(const float4*)&Ws[k][tx * 8];
            float4 b1 = *(const float4*)&Ws[k][tx * 8 + 4];
            u64 b2[4];
            b2[0] = pack2(b0.x, b0.y);
            b2[1] = pack2(b0.z, b0.w);
            b2[2] = pack2(b1.x, b1.y);
            b2[3] = pack2(b1.z, b1.w);

#pragma unroll
            for (int i = 0; i < 8; i++)
#pragma unroll
                for (int j = 0; j < 4; j++) fma2(acc[i][j], a2[i], b2[j]);
        }
        __syncthreads();
    }

    // Epilogue: tx<8 -> g_T ; tx>=8 -> g_ACC (+brel).
    float* Tout = g_T[rel];
    float* Aout = g_ACC[rel];
#pragma unroll
    for (int i = 0; i < 8; i++) {
        int row = row0 + ty * 8 + i;
        if (row >= N) break;
        float c0, c1, c2, c3, c4, c5, c6, c7;
        unpack2(acc[i][0], c0, c1);
        unpack2(acc[i][1], c2, c3);
        unpack2(acc[i][2], c4, c5);
        unpack2(acc[i][3], c6, c7);
        if (tx < 8) {
            int c = tx * 8;
            *(float4*)(Tout + (long)row * D_OUT + c)     = make_float4(c0, c1, c2, c3);
            *(float4*)(Tout + (long)row * D_OUT + c + 4) = make_float4(c4, c5, c6, c7);
        } else {
            int c = (tx - 8) * 8;
            *(float4*)(Aout + (long)row * D_OUT + c) =
                make_float4(c0 + bs[c + 0], c1 + bs[c + 1], c2 + bs[c + 2], c3 + bs[c + 3]);
            *(float4*)(Aout + (long)row * D_OUT + c + 4) =
                make_float4(c4 + bs[c + 4], c5 + bs[c + 5], c6 + bs[c + 6], c7 + bs[c + 7]);
        }
    }
}

// ---------------------------------------------------------------------------
// Kernel B: edge scatter-add in projected 64-dim space, BOTH relations
// (grid.y = rel). 16 threads/edge, vector red to L2. Edges are int32.
// ---------------------------------------------------------------------------
__global__ __launch_bounds__(256) void scatter_kernel(
    const int* __restrict__ edges0, const int* __restrict__ edges1, int E)
{
    const int rel = blockIdx.y;
    const int* __restrict__ edges = rel ? edges1 : edges0;
    const float* __restrict__ T = g_T[rel];
    float* __restrict__ A = g_ACC[rel];

    int idx  = blockIdx.x * blockDim.x + threadIdx.x;
    int e    = idx >> 4;
    int lane = idx & 15;
    if (e >= E) return;

    int src = edges[e];
    int dst = edges[E + e];

    float4 v = *(const float4*)(T + (long)src * D_OUT + lane * 4);
    float* p = A + (long)dst * D_OUT + lane * 4;
    asm volatile("red.global.add.v4.f32 [%0], {%1,%2,%3,%4};"
                 :: "l"(p), "f"(v.x), "f"(v.y), "f"(v.z), "f"(v.w)
                 : "memory");
}

// ---------------------------------------------------------------------------
// Kernel C: fused relu + concat-dot with Wfc + bias. 16 threads/node.
// ---------------------------------------------------------------------------
__global__ __launch_bounds__(256) void output_kernel(
    const float* __restrict__ Wfc, const float* __restrict__ bfc,
    float* __restrict__ out, int N)
{
    __shared__ float wf[128];
    int tid = threadIdx.x;
    if (tid < 128) wf[tid] = Wfc[tid];
    __syncthreads();

    int idx  = blockIdx.x * blockDim.x + tid;
    int node = idx >> 4;
    int lane = idx & 15;
    if (node >= N) return;

    float4 a = *(const float4*)(g_ACC[0] + (long)node * D_OUT + lane * 4);
    float4 b = *(const float4*)(g_ACC[1] + (long)node * D_OUT + lane * 4);

    int c = lane * 4;
    float s = 0.0f;
    s += fmaxf(a.x, 0.f) * wf[c + 0];
    s += fmaxf(a.y, 0.f) * wf[c + 1];
    s += fmaxf(a.z, 0.f) * wf[c + 2];
    s += fmaxf(a.w, 0.f) * wf[c + 3];
    s += fmaxf(b.x, 0.f) * wf[64 + c + 0];
    s += fmaxf(b.y, 0.f) * wf[64 + c + 1];
    s += fmaxf(b.z, 0.f) * wf[64 + c + 2];
    s += fmaxf(b.w, 0.f) * wf[64 + c + 3];

#pragma unroll
    for (int off = 8; off > 0; off >>= 1)
        s += __shfl_down_sync(0xFFFFFFFFu, s, off, 16);

    if (lane == 0) out[node] = s + bfc[0];
}

// ---------------------------------------------------------------------------
extern "C" void kernel_launch(void* const* d_in, const int* in_sizes, int n_in,
                              void* d_out, int out_size)
{
    const float* x0     = (const float*)d_in[0];
    const float* x1     = (const float*)d_in[1];
    const int*   e0     = (const int*)d_in[2];
    const int*   e1     = (const int*)d_in[3];
    const float* Wrel0  = (const float*)d_in[4];
    const float* brel0  = (const float*)d_in[5];
    const float* Wroot0 = (const float*)d_in[6];
    const float* Wrel1  = (const float*)d_in[7];
    const float* brel1  = (const float*)d_in[8];
    const float* Wroot1 = (const float*)d_in[9];
    const float* Wfc    = (const float*)d_in[10];
    const float* bfc    = (const float*)d_in[11];
    float* out = (float*)d_out;

    const int N = in_sizes[0] / D_IN;     // 50000
    const int E = in_sizes[2] / 2;        // 600000

    dim3 tgrid((N + 127) / 128, 2);
    dim3 sgrid((E * 16 + 255) / 256, 2);
    const int oblocks = (N * 16 + 255) / 256;

    transform_kernel<<<tgrid, 256>>>(x0, x1, Wrel0, brel0, Wroot0,
                                     Wrel1, brel1, Wroot1, N);
    scatter_kernel<<<sgrid, 256>>>(e0, e1, E);
    output_kernel<<<oblocks, 256>>>(Wfc, bfc, out, N);
}